// round 16
// baseline (speedup 1.0000x reference)
#include <cuda_runtime.h>
#include <cuda_fp16.h>
#include <cstdint>

#define NB 64
#define MB 128
#define LB 8192
#define DB 64
#define HOURS_C 168

// ---------------- scratch (no runtime allocation allowed) -------------------
__device__ float g_rowsum[LB];
__device__ unsigned char g_need[LB];          // zero-init; re-zeroed by scores tail
__device__ __align__(16) float g_q[(size_t)NB * MB * DB];
__device__ __align__(16) float g_k[(size_t)NB * MB * DB];
__device__ __align__(16) float g_v[(size_t)NB * MB * DB];
__device__ __align__(16) float g_sa[(size_t)NB * MB * DB];
__device__ __align__(16) __half g_Wh[(size_t)LB * DB];

// ---------------- helpers ----------------------------------------------------
__device__ __forceinline__ uint32_t smem_u32(const void* p) {
    uint32_t a;
    asm("{ .reg .u64 t; cvta.to.shared.u64 t, %1; cvt.u32.u64 %0, t; }" : "=r"(a) : "l"(p));
    return a;
}
__device__ __forceinline__ void ldsm_x4(uint32_t* r, uint32_t addr) {
    asm volatile("ldmatrix.sync.aligned.m8n8.x4.shared.b16 {%0,%1,%2,%3}, [%4];"
                 : "=r"(r[0]), "=r"(r[1]), "=r"(r[2]), "=r"(r[3]) : "r"(addr));
}
__device__ __forceinline__ void mma16816(float* c, const uint32_t* a, uint32_t b0, uint32_t b1) {
    asm volatile(
        "mma.sync.aligned.m16n8k16.row.col.f32.f16.f16.f32 "
        "{%0,%1,%2,%3}, {%4,%5,%6,%7}, {%8,%9}, {%0,%1,%2,%3};"
        : "+f"(c[0]), "+f"(c[1]), "+f"(c[2]), "+f"(c[3])
        : "r"(a[0]), "r"(a[1]), "r"(a[2]), "r"(a[3]), "r"(b0), "r"(b1));
}

// ---------------------------------------------------------------------------
// Kernel 0: mark needed rows from traj (flags zeroed by prev run / init)
// ---------------------------------------------------------------------------
__global__ __launch_bounds__(256) void mark_need_kernel(const int* __restrict__ traj) {
    int i = blockIdx.x * 256 + threadIdx.x;
    int loc = traj[3 * i + 1];
    g_need[loc - 1] = 1;
}

// ---------------------------------------------------------------------------
// Kernel 1: conditional row sums — 8192 CTAs, early-exit. LOW-priority stream.
// ---------------------------------------------------------------------------
__global__ __launch_bounds__(256) void rowsum_kernel(const float* __restrict__ mat2s) {
    int l = blockIdx.x;
    if (!g_need[l]) return;
    const float4* row = (const float4*)(mat2s + (size_t)l * LB);
    float s = 0.f;
#pragma unroll
    for (int i = threadIdx.x; i < LB / 4; i += 256) {
        float4 v = row[i];
        s += v.x + v.y + v.z + v.w;
    }
    __shared__ float red[8];
#pragma unroll
    for (int o = 16; o; o >>= 1) s += __shfl_down_sync(~0u, s, o);
    if ((threadIdx.x & 31) == 0) red[threadIdx.x >> 5] = s;
    __syncthreads();
    if (threadIdx.x < 8) {
        s = red[threadIdx.x];
#pragma unroll
        for (int o = 4; o; o >>= 1) s += __shfl_down_sync(0xffu, s, o);
        if (threadIdx.x == 0) g_rowsum[l] = s;
    }
}

// ---------------------------------------------------------------------------
// Kernel 2a: QKV (256 CTAs x 32 rows) + W_out->fp16 fold
// ---------------------------------------------------------------------------
#define LJ 68

extern __shared__ float sm_q[];

__global__ __launch_bounds__(256) void qkv_kernel(
    const int*   __restrict__ traj,
    const float* __restrict__ emb_t,
    const float* __restrict__ emb_l,
    const float* __restrict__ emb_u,
    const float* __restrict__ Wq,
    const float* __restrict__ Wk,
    const float* __restrict__ Wv,
    const float* __restrict__ W_out)
{
    float* joint = sm_q;                   // [32][LJ]
    float* Ws    = joint + 32 * LJ;        // [3][64][LJ]

    const int tid = threadIdx.x;
    const int r0  = blockIdx.x * 32;

    {
        const float4* gw = (const float4*)W_out + (size_t)blockIdx.x * 512;
        __half2* dst = (__half2*)(g_Wh + (size_t)blockIdx.x * 2048);
#pragma unroll
        for (int r = 0; r < 2; r++) {
            int idx = r * 256 + tid;
            float4 w = gw[idx];
            dst[idx * 2 + 0] = __floats2half2_rn(w.x, w.y);
            dst[idx * 2 + 1] = __floats2half2_rn(w.z, w.w);
        }
    }

    for (int i = tid; i < 32 * 64; i += 256) {
        int m = i >> 6, d = i & 63;
        int base = (r0 + m) * 3;
        int u   = traj[base + 0];
        int loc = traj[base + 1];
        int t   = traj[base + 2];
        int ti  = (t - 1) % HOURS_C + 1;
        joint[m * LJ + d] = emb_t[ti * DB + d] + emb_l[loc * DB + d] + emb_u[u * DB + d];
    }
    {
        const float4* Wmats[3] = {(const float4*)Wq, (const float4*)Wk, (const float4*)Wv};
#pragma unroll
        for (int w = 0; w < 3; w++) {
            float* Wsw = Ws + w * 64 * LJ;
            for (int i = tid; i < 64 * 16; i += 256) {
                int rr = i >> 4, c4 = i & 15;
                *(float4*)&Wsw[rr * LJ + c4 * 4] = Wmats[w][i];
            }
        }
    }
    __syncthreads();

    const int ty = tid >> 5;
    const int tx = tid & 31;

    float acc[3][4][2] = {};
#pragma unroll
    for (int j4 = 0; j4 < 16; j4++) {
        float4 a[4];
#pragma unroll
        for (int i = 0; i < 4; i++)
            a[i] = *(const float4*)&joint[(ty * 4 + i) * LJ + j4 * 4];
#pragma unroll
        for (int w = 0; w < 3; w++) {
            const float* Wsw = Ws + w * 64 * LJ;
            float4 b0 = *(const float4*)&Wsw[tx * LJ + j4 * 4];
            float4 b1 = *(const float4*)&Wsw[(tx + 32) * LJ + j4 * 4];
#pragma unroll
            for (int i = 0; i < 4; i++) {
                acc[w][i][0] += a[i].x * b0.x + a[i].y * b0.y + a[i].z * b0.z + a[i].w * b0.w;
                acc[w][i][1] += a[i].x * b1.x + a[i].y * b1.y + a[i].z * b1.z + a[i].w * b1.w;
            }
        }
    }
    float* outs[3] = {g_q, g_k, g_v};
#pragma unroll
    for (int w = 0; w < 3; w++) {
        float* op = outs[w] + (size_t)(r0 + ty * 4) * DB;
#pragma unroll
        for (int i = 0; i < 4; i++) {
            op[i * DB + tx]      = acc[w][i][0];
            op[i * DB + tx + 32] = acc[w][i][1];
        }
    }
}

// ---------------------------------------------------------------------------
// Kernel 2b: scores + softmax + attn@v -> g_sa (f32). NO rowsum dependency.
// grid (8, 64), MT=16, phased k/v buffer + register v-prefetch (4 CTAs/SM).
// Tail of block 0/1 re-zeros g_need for the next replay.
// ---------------------------------------------------------------------------
#define LSC 132
#define MT 16

extern __shared__ float sm_s[];

__global__ __launch_bounds__(256) void scores_kernel(
    const float* __restrict__ mat1,
    const int*   __restrict__ traj_len,
    const float* __restrict__ emb_su,
    const float* __restrict__ emb_sl,
    const float* __restrict__ emb_tu,
    const float* __restrict__ emb_tl)
{
    float* qs   = sm_s;                    // [MT][LJ]
    float* kv   = qs + MT * LJ;            // [128][LJ] (k, then v)
    float* sc   = kv + 128 * LJ;           // [MT][LSC]
    float* scal = sc + MT * LSC;           // 8

    const int n   = blockIdx.y;
    const int m0  = blockIdx.x * MT;
    const int tid = threadIdx.x;
    const int len = traj_len[n];

    if (tid < 8) {
        int which = tid >> 1, row = tid & 1;
        const float* e = (which == 0) ? emb_sl : (which == 1) ? emb_su
                       : (which == 2) ? emb_tl : emb_tu;
        float s = 0.f;
#pragma unroll
        for (int d = 0; d < DB; d++) s += e[row * DB + d];
        scal[tid] = s;
    }

    {
        const float4* gq = (const float4*)(g_q + (size_t)(n * MB + m0) * DB);
        for (int i = tid; i < MT * 16; i += 256) {
            int rr = i >> 4, c4 = i & 15;
            *(float4*)&qs[rr * LJ + c4 * 4] = gq[i];
        }
        const float4* gk = (const float4*)(g_k + (size_t)n * MB * DB);
        for (int i = tid; i < 128 * 16; i += 256) {
            int rr = i >> 4, c4 = i & 15;
            *(float4*)&kv[rr * LJ + c4 * 4] = gk[i];
        }
    }
    __syncthreads();

    float4 vreg[8];
    {
        const float4* gv = (const float4*)(g_v + (size_t)n * MB * DB);
#pragma unroll
        for (int r = 0; r < 8; r++) vreg[r] = gv[r * 256 + tid];
    }

    const int ty = tid >> 5;      // 2 m-rows each
    const int tx = tid & 31;

    // ---- scores MTx128 ----
    {
        float acc[2][4] = {};
#pragma unroll
        for (int j4 = 0; j4 < 16; j4++) {
            float4 b[4];
#pragma unroll
            for (int pp = 0; pp < 4; pp++)
                b[pp] = *(const float4*)&kv[(tx + pp * 32) * LJ + j4 * 4];
#pragma unroll
            for (int i = 0; i < 2; i++) {
                float4 a = *(const float4*)&qs[(ty * 2 + i) * LJ + j4 * 4];
#pragma unroll
                for (int pp = 0; pp < 4; pp++)
                    acc[i][pp] += a.x * b[pp].x + a.y * b[pp].y + a.z * b[pp].z + a.w * b[pp].w;
            }
        }
        float s0 = scal[0], s1 = scal[1], s2 = scal[2], s3 = scal[3];
        float s4 = scal[4], s5 = scal[5], s6 = scal[6], s7 = scal[7];
#pragma unroll
        for (int i = 0; i < 2; i++) {
            int mg = m0 + ty * 2 + i;
            bool vm = mg < len;
            const float2* mrow = (const float2*)mat1 + (size_t)(n * MB + mg) * MB;
#pragma unroll
            for (int pp = 0; pp < 4; pp++) {
                int p = tx + pp * 32;
                bool msk = vm && (p < len);
                float2 dd = mrow[p];
                float ssl = msk ? s1 : s0;
                float ssu = msk ? s3 : s2;
                float stl = msk ? s5 : s4;
                float stu = msk ? s7 : s6;
                float delta = (ssl * (100.0f - dd.x) + ssu * dd.x) * 0.01f
                            + (stl * (500.0f - dd.y) + stu * dd.y) * 0.002f;
                sc[(ty * 2 + i) * LSC + p] = acc[i][pp] + delta;
            }
        }
    }
    __syncthreads();

    // ---- softmax + ragged mask ----
    {
        int wid = tid >> 5, lane = tid & 31;
        for (int m2 = wid; m2 < MT; m2 += 8) {
            float v0 = sc[m2 * LSC + lane];
            float v1 = sc[m2 * LSC + lane + 32];
            float v2 = sc[m2 * LSC + lane + 64];
            float v3 = sc[m2 * LSC + lane + 96];
            float mx = fmaxf(fmaxf(v0, v1), fmaxf(v2, v3));
#pragma unroll
            for (int o = 16; o; o >>= 1) mx = fmaxf(mx, __shfl_xor_sync(~0u, mx, o));
            float e0 = __expf(v0 - mx), e1 = __expf(v1 - mx);
            float e2 = __expf(v2 - mx), e3 = __expf(v3 - mx);
            float sum = e0 + e1 + e2 + e3;
#pragma unroll
            for (int o = 16; o; o >>= 1) sum += __shfl_xor_sync(~0u, sum, o);
            float inv = 1.0f / sum;
            bool vm2 = (m0 + m2) < len;
            sc[m2 * LSC + lane]      = (vm2 && (lane      < len)) ? e0 * inv : 0.f;
            sc[m2 * LSC + lane + 32] = (vm2 && (lane + 32 < len)) ? e1 * inv : 0.f;
            sc[m2 * LSC + lane + 64] = (vm2 && (lane + 64 < len)) ? e2 * inv : 0.f;
            sc[m2 * LSC + lane + 96] = (vm2 && (lane + 96 < len)) ? e3 * inv : 0.f;
        }
    }
    __syncthreads();

    // store prefetched v over k
    {
#pragma unroll
        for (int r = 0; r < 8; r++) {
            int idx = r * 256 + tid;
            int rr = idx >> 4, c4 = idx & 15;
            *(float4*)&kv[rr * LJ + c4 * 4] = vreg[r];
        }
    }
    __syncthreads();

    // ---- attn @ v (MTx64) -> g_sa ----
    {
        float acc[2][2] = {};
#pragma unroll
        for (int p4 = 0; p4 < 32; p4++) {
            float b0[4], b1[4];
#pragma unroll
            for (int r = 0; r < 4; r++) {
                b0[r] = kv[(p4 * 4 + r) * LJ + tx];
                b1[r] = kv[(p4 * 4 + r) * LJ + tx + 32];
            }
#pragma unroll
            for (int i = 0; i < 2; i++) {
                float4 a = *(const float4*)&sc[(ty * 2 + i) * LSC + p4 * 4];
                acc[i][0] += a.x * b0[0] + a.y * b0[1] + a.z * b0[2] + a.w * b0[3];
                acc[i][1] += a.x * b1[0] + a.y * b1[1] + a.z * b1[2] + a.w * b1[3];
            }
        }
#pragma unroll
        for (int i = 0; i < 2; i++) {
            size_t base = (size_t)(n * MB + m0 + ty * 2 + i) * DB;
            g_sa[base + tx]      = acc[i][0];
            g_sa[base + tx + 32] = acc[i][1];
        }
    }

    // re-zero flags for next replay (rowsum has already consumed them:
    // the GEMM following the join serializes, but flags are only read by
    // rowsum which completed before the join in program order of next replay)
    if (blockIdx.y == 0 && blockIdx.x < 2)
        ((uint4*)g_need)[blockIdx.x * 256 + tid] = uint4{0, 0, 0, 0};
}

// ---------------------------------------------------------------------------
// Kernel 3: fp16 GEMM, 128x256 macro-tile/CTA, xmult FUSED into A-load.
// Each CTA's 128 rows = exactly one n (blockIdx.y). grid (32, 64).
// ---------------------------------------------------------------------------
#define SA 72
#define TILE_HB (128 * SA)

extern __shared__ __align__(16) __half sm_g[];

__global__ __launch_bounds__(256) void out_gemm_mma(
    const int*   __restrict__ traj,
    const float* __restrict__ vec,
    const int*   __restrict__ traj_len,
    const float* __restrict__ emb_su,
    const float* __restrict__ emb_sl,
    const float* __restrict__ emb_tu,
    const float* __restrict__ emb_tl,
    const float* __restrict__ b_out,
    float*       __restrict__ out)
{
    __half* Ah = sm_g;
    __half* Bh = Ah + TILE_HB;
    float* sbias = (float*)(Bh + TILE_HB);

    const int tid  = threadIdx.x;
    const int wid  = tid >> 5;
    const int lane = tid & 31;
    const int wm   = wid & 1;
    const int wn   = wid >> 1;
    const int n    = blockIdx.y;            // 128 rows = one batch
    const int rB   = n * 128;
    const int lB0  = blockIdx.x * 256;
    const int len  = traj_len[n];

    // ---- fused A-load: g_sa(f32) * delta2 -> fp16 smem tile ----
    {
        const float4* gsa = (const float4*)(g_sa + (size_t)rB * DB);
#pragma unroll
        for (int it = 0; it < 4; it++) {
            int idx = it * 256 + tid;          // 1024 chunks of 8 f32
            int row = idx >> 3, ch = idx & 7;  // d0 = ch*8
            bool vm = row < len;
            int m1 = vm ? 1 : 0;
            int loc = traj[(rB + row) * 3 + 1];
            float ds_sum = vm ? g_rowsum[loc - 1] : 0.f;
            float ve = vec[rB + row];
            const float Lf = 8192.0f;
            float S_vsl = ds_sum;
            float S_vsu = 100.0f * Lf - ds_sum;
            float S_vtl = ve * Lf;
            float S_vtu = (500.0f - ve) * Lf;

            float4 a0 = gsa[idx * 2];
            float4 a1 = gsa[idx * 2 + 1];
            float av[8] = {a0.x, a0.y, a0.z, a0.w, a1.x, a1.y, a1.z, a1.w};
            __half hv[8];
#pragma unroll
            for (int j = 0; j < 8; j++) {
                int d = ch * 8 + j;
                float d2 = (emb_sl[m1 * DB + d] * S_vsu + emb_su[m1 * DB + d] * S_vsl) * 0.01f
                         + (emb_tl[m1 * DB + d] * S_vtu + emb_tu[m1 * DB + d] * S_vtl) * 0.002f;
                hv[j] = __float2half(av[j] * d2);
            }
            *(uint4*)(Ah + row * SA + ch * 8) = *(uint4*)hv;
        }
    }

    const uint32_t sb = smem_u32(sm_g);
    const uint32_t aH = sb;
    const uint32_t bH = sb + TILE_HB * 2;

    const int lrow = lane & 15;
    const int lcol = (lane >> 4) * 8;
    const int gr = lane >> 2;
    const int gc = (lane & 3) * 2;

#pragma unroll 1
    for (int half = 0; half < 2; half++) {
        const int lB = lB0 + half * 128;
        if (half == 1) __syncthreads();

        {
            const uint4* gB = (const uint4*)(g_Wh + (size_t)lB * DB);
#pragma unroll
            for (int it = 0; it < 4; it++) {
                int idx = it * 256 + tid;
                int row = idx >> 3, ch = idx & 7;
                *(uint4*)(Bh + row * SA + ch * 8) = gB[idx];
            }
            if (tid < 128) sbias[tid] = b_out[lB + tid];
        }
        __syncthreads();

        float acc[4][4][4];
#pragma unroll
        for (int i = 0; i < 4; i++)
#pragma unroll
            for (int j = 0; j < 4; j++)
#pragma unroll
                for (int c = 0; c < 4; c++) acc[i][j][c] = 0.f;

#pragma unroll
        for (int ks = 0; ks < 4; ks++) {
            const uint32_t koff = (uint32_t)(ks * 16 + lcol) * 2;
            uint32_t fA[4][4];
#pragma unroll
            for (int mt = 0; mt < 4; mt++) {
                uint32_t ro = (uint32_t)((wm * 64 + mt * 16 + lrow) * SA) * 2 + koff;
                ldsm_x4(fA[mt], aH + ro);
            }
            uint32_t fB[2][4];
#pragma unroll
            for (int nt2 = 0; nt2 < 2; nt2++) {
                uint32_t ro = (uint32_t)((wn * 32 + nt2 * 16 + lrow) * SA) * 2 + koff;
                ldsm_x4(fB[nt2], bH + ro);
            }
#pragma unroll
            for (int mt = 0; mt < 4; mt++)
#pragma unroll
                for (int nt = 0; nt < 4; nt++) {
                    const int h = nt >> 1, o = nt & 1;
                    mma16816(acc[mt][nt], fA[mt], fB[h][o], fB[h][o + 2]);
                }
        }

#pragma unroll
        for (int mt = 0; mt < 4; mt++) {
#pragma unroll
            for (int nt = 0; nt < 4; nt++) {
                int col = wn * 32 + nt * 8 + gc;
                float b0 = sbias[col], b1 = sbias[col + 1];
                size_t r0 = (size_t)(rB + wm * 64 + mt * 16 + gr) * LB + lB + col;
                float2 v0 = {acc[mt][nt][0] + b0, acc[mt][nt][1] + b1};
                float2 v1 = {acc[mt][nt][2] + b0, acc[mt][nt][3] + b1};
                __stcs((float2*)(out + r0), v0);
                __stcs((float2*)(out + r0 + 8 * LB), v1);
            }
        }
    }
}

// ---------------------------------------------------------------------------
// Side stream (LOW priority) + events, created once pre-main.
// ---------------------------------------------------------------------------
struct _SideStream {
    cudaStream_t s2;
    cudaEvent_t ef, ej;
    _SideStream() {
        cudaFree(0);
        int lo, hi;
        cudaDeviceGetStreamPriorityRange(&lo, &hi);
        cudaStreamCreateWithPriority(&s2, cudaStreamNonBlocking, lo);
        cudaEventCreateWithFlags(&ef, cudaEventDisableTiming);
        cudaEventCreateWithFlags(&ej, cudaEventDisableTiming);
    }
};
static _SideStream g_ss;

// ---------------------------------------------------------------------------
extern "C" void kernel_launch(void* const* d_in, const int* in_sizes, int n_in,
                              void* d_out, int out_size) {
    const int*   traj     = (const int*)  d_in[0];
    const float* mat1     = (const float*)d_in[1];
    const float* mat2s    = (const float*)d_in[2];
    const float* vec      = (const float*)d_in[3];
    const int*   traj_len = (const int*)  d_in[4];
    const float* emb_t    = (const float*)d_in[5];
    const float* emb_l    = (const float*)d_in[6];
    const float* emb_u    = (const float*)d_in[7];
    const float* emb_su   = (const float*)d_in[8];
    const float* emb_sl   = (const float*)d_in[9];
    const float* emb_tu   = (const float*)d_in[10];
    const float* emb_tl   = (const float*)d_in[11];
    const float* Wq       = (const float*)d_in[12];
    const float* Wk       = (const float*)d_in[13];
    const float* Wv       = (const float*)d_in[14];
    const float* W_out    = (const float*)d_in[15];
    const float* b_out    = (const float*)d_in[16];
    float* out = (float*)d_out;

    const int QKV_SMEM = (32 * LJ + 3 * 64 * LJ) * (int)sizeof(float);
    const int SC_SMEM  = (MT * LJ + 128 * LJ + MT * LSC + 8) * (int)sizeof(float);
    const int GEMM_SMEM = (2 * TILE_HB) * 2 + 128 * (int)sizeof(float);
    cudaFuncSetAttribute(qkv_kernel,    cudaFuncAttributeMaxDynamicSharedMemorySize, QKV_SMEM);
    cudaFuncSetAttribute(scores_kernel, cudaFuncAttributeMaxDynamicSharedMemorySize, SC_SMEM);
    cudaFuncSetAttribute(out_gemm_mma,  cudaFuncAttributeMaxDynamicSharedMemorySize, GEMM_SMEM);

    // main: mark; fork rowsum onto LOW-priority stream
    mark_need_kernel<<<NB * MB / 256, 256>>>(traj);
    cudaEventRecord(g_ss.ef, 0);
    cudaStreamWaitEvent(g_ss.s2, g_ss.ef, 0);
    rowsum_kernel<<<LB, 256, 0, g_ss.s2>>>(mat2s);
    cudaEventRecord(g_ss.ej, g_ss.s2);

    // main stream: attention pipeline (no rowsum dependency)
    qkv_kernel<<<(NB * MB) / 32, 256, QKV_SMEM>>>(traj, emb_t, emb_l, emb_u,
                                                  Wq, Wk, Wv, W_out);
    dim3 sg(MB / MT, NB);
    scores_kernel<<<sg, 256, SC_SMEM>>>(mat1, traj_len, emb_su, emb_sl, emb_tu, emb_tl);

    // join (GEMM consumes g_rowsum via fused xmult), then GEMM
    cudaStreamWaitEvent(0, g_ss.ej, 0);
    dim3 grid(LB / 256, NB);
    out_gemm_mma<<<grid, 256, GEMM_SMEM>>>(traj, vec, traj_len,
                                           emb_su, emb_sl, emb_tu, emb_tl,
                                           b_out, out);
}

// round 17
// speedup vs baseline: 1.1981x; 1.1981x over previous
#include <cuda_runtime.h>
#include <cuda_fp16.h>
#include <cstdint>

#define NB 64
#define MB 128
#define LB 8192
#define DB 64
#define HOURS_C 168

// ---------------- scratch (no runtime allocation allowed) -------------------
__device__ float g_rowsum[LB];
__device__ unsigned char g_need[LB];          // zero-init; re-zeroed by scores tail
__device__ __align__(16) float g_q[(size_t)NB * MB * DB];
__device__ __align__(16) float g_k[(size_t)NB * MB * DB];
__device__ __align__(16) float g_v[(size_t)NB * MB * DB];
__device__ __align__(16) __half g_Xh[(size_t)NB * MB * DB];
__device__ __align__(16) __half g_Wh[(size_t)LB * DB];

// ---------------- helpers ----------------------------------------------------
__device__ __forceinline__ uint32_t smem_u32(const void* p) {
    uint32_t a;
    asm("{ .reg .u64 t; cvta.to.shared.u64 t, %1; cvt.u32.u64 %0, t; }" : "=r"(a) : "l"(p));
    return a;
}
__device__ __forceinline__ void ldsm_x4(uint32_t* r, uint32_t addr) {
    asm volatile("ldmatrix.sync.aligned.m8n8.x4.shared.b16 {%0,%1,%2,%3}, [%4];"
                 : "=r"(r[0]), "=r"(r[1]), "=r"(r[2]), "=r"(r[3]) : "r"(addr));
}
__device__ __forceinline__ void mma16816(float* c, const uint32_t* a, uint32_t b0, uint32_t b1) {
    asm volatile(
        "mma.sync.aligned.m16n8k16.row.col.f32.f16.f16.f32 "
        "{%0,%1,%2,%3}, {%4,%5,%6,%7}, {%8,%9}, {%0,%1,%2,%3};"
        : "+f"(c[0]), "+f"(c[1]), "+f"(c[2]), "+f"(c[3])
        : "r"(a[0]), "r"(a[1]), "r"(a[2]), "r"(a[3]), "r"(b0), "r"(b1));
}

// ---------------------------------------------------------------------------
// Kernel 0: mark needed rows from traj (flags zeroed by prev run / init)
// ---------------------------------------------------------------------------
__global__ __launch_bounds__(256) void mark_need_kernel(const int* __restrict__ traj) {
    int i = blockIdx.x * 256 + threadIdx.x;
    int loc = traj[3 * i + 1];
    g_need[loc - 1] = 1;
}

// ---------------------------------------------------------------------------
// Kernel 1: conditional row sums — 8192 CTAs, early-exit. LOW-priority stream.
// ---------------------------------------------------------------------------
__global__ __launch_bounds__(256) void rowsum_kernel(const float* __restrict__ mat2s) {
    int l = blockIdx.x;
    if (!g_need[l]) return;
    const float4* row = (const float4*)(mat2s + (size_t)l * LB);
    float s = 0.f;
#pragma unroll
    for (int i = threadIdx.x; i < LB / 4; i += 256) {
        float4 v = row[i];
        s += v.x + v.y + v.z + v.w;
    }
    __shared__ float red[8];
#pragma unroll
    for (int o = 16; o; o >>= 1) s += __shfl_down_sync(~0u, s, o);
    if ((threadIdx.x & 31) == 0) red[threadIdx.x >> 5] = s;
    __syncthreads();
    if (threadIdx.x < 8) {
        s = red[threadIdx.x];
#pragma unroll
        for (int o = 4; o; o >>= 1) s += __shfl_down_sync(0xffu, s, o);
        if (threadIdx.x == 0) g_rowsum[l] = s;
    }
}

// ---------------------------------------------------------------------------
// Kernel 2a: QKV (256 CTAs x 32 rows) + W_out->fp16 fold
// ---------------------------------------------------------------------------
#define LJ 68

extern __shared__ float sm_q[];

__global__ __launch_bounds__(256) void qkv_kernel(
    const int*   __restrict__ traj,
    const float* __restrict__ emb_t,
    const float* __restrict__ emb_l,
    const float* __restrict__ emb_u,
    const float* __restrict__ Wq,
    const float* __restrict__ Wk,
    const float* __restrict__ Wv,
    const float* __restrict__ W_out)
{
    float* joint = sm_q;                   // [32][LJ]
    float* Ws    = joint + 32 * LJ;        // [3][64][LJ]

    const int tid = threadIdx.x;
    const int r0  = blockIdx.x * 32;

    {
        const float4* gw = (const float4*)W_out + (size_t)blockIdx.x * 512;
        __half2* dst = (__half2*)(g_Wh + (size_t)blockIdx.x * 2048);
#pragma unroll
        for (int r = 0; r < 2; r++) {
            int idx = r * 256 + tid;
            float4 w = gw[idx];
            dst[idx * 2 + 0] = __floats2half2_rn(w.x, w.y);
            dst[idx * 2 + 1] = __floats2half2_rn(w.z, w.w);
        }
    }

    for (int i = tid; i < 32 * 64; i += 256) {
        int m = i >> 6, d = i & 63;
        int base = (r0 + m) * 3;
        int u   = traj[base + 0];
        int loc = traj[base + 1];
        int t   = traj[base + 2];
        int ti  = (t - 1) % HOURS_C + 1;
        joint[m * LJ + d] = emb_t[ti * DB + d] + emb_l[loc * DB + d] + emb_u[u * DB + d];
    }
    {
        const float4* Wmats[3] = {(const float4*)Wq, (const float4*)Wk, (const float4*)Wv};
#pragma unroll
        for (int w = 0; w < 3; w++) {
            float* Wsw = Ws + w * 64 * LJ;
            for (int i = tid; i < 64 * 16; i += 256) {
                int rr = i >> 4, c4 = i & 15;
                *(float4*)&Wsw[rr * LJ + c4 * 4] = Wmats[w][i];
            }
        }
    }
    __syncthreads();

    const int ty = tid >> 5;
    const int tx = tid & 31;

    float acc[3][4][2] = {};
#pragma unroll
    for (int j4 = 0; j4 < 16; j4++) {
        float4 a[4];
#pragma unroll
        for (int i = 0; i < 4; i++)
            a[i] = *(const float4*)&joint[(ty * 4 + i) * LJ + j4 * 4];
#pragma unroll
        for (int w = 0; w < 3; w++) {
            const float* Wsw = Ws + w * 64 * LJ;
            float4 b0 = *(const float4*)&Wsw[tx * LJ + j4 * 4];
            float4 b1 = *(const float4*)&Wsw[(tx + 32) * LJ + j4 * 4];
#pragma unroll
            for (int i = 0; i < 4; i++) {
                acc[w][i][0] += a[i].x * b0.x + a[i].y * b0.y + a[i].z * b0.z + a[i].w * b0.w;
                acc[w][i][1] += a[i].x * b1.x + a[i].y * b1.y + a[i].z * b1.z + a[i].w * b1.w;
            }
        }
    }
    float* outs[3] = {g_q, g_k, g_v};
#pragma unroll
    for (int w = 0; w < 3; w++) {
        float* op = outs[w] + (size_t)(r0 + ty * 4) * DB;
#pragma unroll
        for (int i = 0; i < 4; i++) {
            op[i * DB + tx]      = acc[w][i][0];
            op[i * DB + tx + 32] = acc[w][i][1];
        }
    }
}

// ---------------------------------------------------------------------------
// Kernel 2b: scores + softmax + attn@v + delta2 (fused xmult) -> g_Xh (fp16)
// grid (4, 64), MT=32, phased k/v buffer + register v-prefetch. Runs AFTER
// the rowsum join. Tail re-zeros g_need for the next replay.
// ---------------------------------------------------------------------------
#define LSC 132
#define MT 32

extern __shared__ float sm_s[];

__global__ __launch_bounds__(256) void scores_kernel(
    const int*   __restrict__ traj,
    const float* __restrict__ mat1,
    const float* __restrict__ vec,
    const int*   __restrict__ traj_len,
    const float* __restrict__ emb_su,
    const float* __restrict__ emb_sl,
    const float* __restrict__ emb_tu,
    const float* __restrict__ emb_tl)
{
    float* qs   = sm_s;                    // [MT][LJ]
    float* kv   = qs + MT * LJ;            // [128][LJ] (k, then v)
    float* sc   = kv + 128 * LJ;           // [MT][LSC]
    float* scal = sc + MT * LSC;           // 8

    const int n   = blockIdx.y;
    const int m0  = blockIdx.x * MT;
    const int tid = threadIdx.x;
    const int len = traj_len[n];

    if (tid < 8) {
        int which = tid >> 1, row = tid & 1;
        const float* e = (which == 0) ? emb_sl : (which == 1) ? emb_su
                       : (which == 2) ? emb_tl : emb_tu;
        float s = 0.f;
#pragma unroll
        for (int d = 0; d < DB; d++) s += e[row * DB + d];
        scal[tid] = s;
    }

    {
        const float4* gq = (const float4*)(g_q + (size_t)(n * MB + m0) * DB);
        for (int i = tid; i < MT * 16; i += 256) {
            int rr = i >> 4, c4 = i & 15;
            *(float4*)&qs[rr * LJ + c4 * 4] = gq[i];
        }
        const float4* gk = (const float4*)(g_k + (size_t)n * MB * DB);
        for (int i = tid; i < 128 * 16; i += 256) {
            int rr = i >> 4, c4 = i & 15;
            *(float4*)&kv[rr * LJ + c4 * 4] = gk[i];
        }
    }
    __syncthreads();

    float4 vreg[8];
    {
        const float4* gv = (const float4*)(g_v + (size_t)n * MB * DB);
#pragma unroll
        for (int r = 0; r < 8; r++) vreg[r] = gv[r * 256 + tid];
    }

    const int ty = tid >> 5;      // 4 m-rows each
    const int tx = tid & 31;

    // ---- scores MTx128 ----
    {
        float acc[4][4] = {};
#pragma unroll
        for (int j4 = 0; j4 < 16; j4++) {
            float4 b[4];
#pragma unroll
            for (int pp = 0; pp < 4; pp++)
                b[pp] = *(const float4*)&kv[(tx + pp * 32) * LJ + j4 * 4];
#pragma unroll
            for (int i = 0; i < 4; i++) {
                float4 a = *(const float4*)&qs[(ty * 4 + i) * LJ + j4 * 4];
#pragma unroll
                for (int pp = 0; pp < 4; pp++)
                    acc[i][pp] += a.x * b[pp].x + a.y * b[pp].y + a.z * b[pp].z + a.w * b[pp].w;
            }
        }
        float s0 = scal[0], s1 = scal[1], s2 = scal[2], s3 = scal[3];
        float s4 = scal[4], s5 = scal[5], s6 = scal[6], s7 = scal[7];
#pragma unroll
        for (int i = 0; i < 4; i++) {
            int mg = m0 + ty * 4 + i;
            bool vm = mg < len;
            const float2* mrow = (const float2*)mat1 + (size_t)(n * MB + mg) * MB;
#pragma unroll
            for (int pp = 0; pp < 4; pp++) {
                int p = tx + pp * 32;
                bool msk = vm && (p < len);
                float2 dd = mrow[p];
                float ssl = msk ? s1 : s0;
                float ssu = msk ? s3 : s2;
                float stl = msk ? s5 : s4;
                float stu = msk ? s7 : s6;
                float delta = (ssl * (100.0f - dd.x) + ssu * dd.x) * 0.01f
                            + (stl * (500.0f - dd.y) + stu * dd.y) * 0.002f;
                sc[(ty * 4 + i) * LSC + p] = acc[i][pp] + delta;
            }
        }
    }
    __syncthreads();

    // ---- softmax + ragged mask ----
    {
        int wid = tid >> 5, lane = tid & 31;
        for (int m2 = wid; m2 < MT; m2 += 8) {
            float v0 = sc[m2 * LSC + lane];
            float v1 = sc[m2 * LSC + lane + 32];
            float v2 = sc[m2 * LSC + lane + 64];
            float v3 = sc[m2 * LSC + lane + 96];
            float mx = fmaxf(fmaxf(v0, v1), fmaxf(v2, v3));
#pragma unroll
            for (int o = 16; o; o >>= 1) mx = fmaxf(mx, __shfl_xor_sync(~0u, mx, o));
            float e0 = __expf(v0 - mx), e1 = __expf(v1 - mx);
            float e2 = __expf(v2 - mx), e3 = __expf(v3 - mx);
            float sum = e0 + e1 + e2 + e3;
#pragma unroll
            for (int o = 16; o; o >>= 1) sum += __shfl_xor_sync(~0u, sum, o);
            float inv = 1.0f / sum;
            bool vm2 = (m0 + m2) < len;
            sc[m2 * LSC + lane]      = (vm2 && (lane      < len)) ? e0 * inv : 0.f;
            sc[m2 * LSC + lane + 32] = (vm2 && (lane + 32 < len)) ? e1 * inv : 0.f;
            sc[m2 * LSC + lane + 64] = (vm2 && (lane + 64 < len)) ? e2 * inv : 0.f;
            sc[m2 * LSC + lane + 96] = (vm2 && (lane + 96 < len)) ? e3 * inv : 0.f;
        }
    }
    __syncthreads();

    // store prefetched v over k
    {
#pragma unroll
        for (int r = 0; r < 8; r++) {
            int idx = r * 256 + tid;
            int rr = idx >> 4, c4 = idx & 15;
            *(float4*)&kv[rr * LJ + c4 * 4] = vreg[r];
        }
    }
    __syncthreads();

    // ---- attn @ v (MTx64) + fused delta2 -> g_Xh (fp16) ----
    {
        float acc[4][2] = {};
#pragma unroll
        for (int p4 = 0; p4 < 32; p4++) {
            float b0[4], b1[4];
#pragma unroll
            for (int r = 0; r < 4; r++) {
                b0[r] = kv[(p4 * 4 + r) * LJ + tx];
                b1[r] = kv[(p4 * 4 + r) * LJ + tx + 32];
            }
#pragma unroll
            for (int i = 0; i < 4; i++) {
                float4 a = *(const float4*)&sc[(ty * 4 + i) * LSC + p4 * 4];
                acc[i][0] += a.x * b0[0] + a.y * b0[1] + a.z * b0[2] + a.w * b0[3];
                acc[i][1] += a.x * b1[0] + a.y * b1[1] + a.z * b1[2] + a.w * b1[3];
            }
        }
#pragma unroll
        for (int i = 0; i < 4; i++) {
            int mg = m0 + ty * 4 + i;
            bool vm = mg < len;
            int m1 = vm ? 1 : 0;
            int loc = traj[(n * MB + mg) * 3 + 1];
            float ds_sum = vm ? g_rowsum[loc - 1] : 0.f;
            float ve = vec[n * MB + mg];
            const float Lf = 8192.0f;
            float S_vsl = ds_sum;
            float S_vsu = 100.0f * Lf - ds_sum;
            float S_vtl = ve * Lf;
            float S_vtu = (500.0f - ve) * Lf;
            size_t base = (size_t)(n * MB + mg) * DB;
#pragma unroll
            for (int dd = 0; dd < 2; dd++) {
                int d = tx + dd * 32;
                float d2 = (emb_sl[m1 * DB + d] * S_vsu + emb_su[m1 * DB + d] * S_vsl) * 0.01f
                         + (emb_tl[m1 * DB + d] * S_vtu + emb_tu[m1 * DB + d] * S_vtl) * 0.002f;
                g_Xh[base + d] = __float2half(acc[i][dd] * d2);
            }
        }
    }

    // re-zero flags for next replay (rowsum already consumed them)
    if (blockIdx.y == 0 && blockIdx.x < 2)
        ((uint4*)g_need)[blockIdx.x * 256 + tid] = uint4{0, 0, 0, 0};
}

// ---------------------------------------------------------------------------
// Kernel 3: fp16 GEMM, 128x256 macro-tile/CTA, A loaded once (R15 version).
// grid (32, 64) = 2048 CTAs.
// ---------------------------------------------------------------------------
#define SA 72
#define TILE_HB (128 * SA)

extern __shared__ __align__(16) __half sm_g[];

__global__ __launch_bounds__(256) void out_gemm_mma(
    const float* __restrict__ b_out, float* __restrict__ out)
{
    __half* Ah = sm_g;
    __half* Bh = Ah + TILE_HB;
    float* sbias = (float*)(Bh + TILE_HB);

    const int tid  = threadIdx.x;
    const int wid  = tid >> 5;
    const int lane = tid & 31;
    const int wm   = wid & 1;
    const int wn   = wid >> 1;
    const int rB  = blockIdx.y * 128;
    const int lB0 = blockIdx.x * 256;

    {
        const uint4* gA = (const uint4*)(g_Xh + (size_t)rB * DB);
#pragma unroll
        for (int it = 0; it < 4; it++) {
            int idx = it * 256 + tid;
            int row = idx >> 3, ch = idx & 7;
            *(uint4*)(Ah + row * SA + ch * 8) = gA[idx];
        }
    }

    const uint32_t sb = smem_u32(sm_g);
    const uint32_t aH = sb;
    const uint32_t bH = sb + TILE_HB * 2;

    const int lrow = lane & 15;
    const int lcol = (lane >> 4) * 8;
    const int gr = lane >> 2;
    const int gc = (lane & 3) * 2;

#pragma unroll 1
    for (int half = 0; half < 2; half++) {
        const int lB = lB0 + half * 128;
        if (half == 1) __syncthreads();

        {
            const uint4* gB = (const uint4*)(g_Wh + (size_t)lB * DB);
#pragma unroll
            for (int it = 0; it < 4; it++) {
                int idx = it * 256 + tid;
                int row = idx >> 3, ch = idx & 7;
                *(uint4*)(Bh + row * SA + ch * 8) = gB[idx];
            }
            if (tid < 128) sbias[tid] = b_out[lB + tid];
        }
        __syncthreads();

        float acc[4][4][4];
#pragma unroll
        for (int i = 0; i < 4; i++)
#pragma unroll
            for (int j = 0; j < 4; j++)
#pragma unroll
                for (int c = 0; c < 4; c++) acc[i][j][c] = 0.f;

#pragma unroll
        for (int ks = 0; ks < 4; ks++) {
            const uint32_t koff = (uint32_t)(ks * 16 + lcol) * 2;
            uint32_t fA[4][4];
#pragma unroll
            for (int mt = 0; mt < 4; mt++) {
                uint32_t ro = (uint32_t)((wm * 64 + mt * 16 + lrow) * SA) * 2 + koff;
                ldsm_x4(fA[mt], aH + ro);
            }
            uint32_t fB[2][4];
#pragma unroll
            for (int nt2 = 0; nt2 < 2; nt2++) {
                uint32_t ro = (uint32_t)((wn * 32 + nt2 * 16 + lrow) * SA) * 2 + koff;
                ldsm_x4(fB[nt2], bH + ro);
            }
#pragma unroll
            for (int mt = 0; mt < 4; mt++)
#pragma unroll
                for (int nt = 0; nt < 4; nt++) {
                    const int h = nt >> 1, o = nt & 1;
                    mma16816(acc[mt][nt], fA[mt], fB[h][o], fB[h][o + 2]);
                }
        }

#pragma unroll
        for (int mt = 0; mt < 4; mt++) {
#pragma unroll
            for (int nt = 0; nt < 4; nt++) {
                int col = wn * 32 + nt * 8 + gc;
                float b0 = sbias[col], b1 = sbias[col + 1];
                size_t r0 = (size_t)(rB + wm * 64 + mt * 16 + gr) * LB + lB + col;
                float2 v0 = {acc[mt][nt][0] + b0, acc[mt][nt][1] + b1};
                float2 v1 = {acc[mt][nt][2] + b0, acc[mt][nt][3] + b1};
                __stcs((float2*)(out + r0), v0);
                __stcs((float2*)(out + r0 + 8 * LB), v1);
            }
        }
    }
}

// ---------------------------------------------------------------------------
// Side stream (LOW priority) + events, created once pre-main.
// ---------------------------------------------------------------------------
struct _SideStream {
    cudaStream_t s2;
    cudaEvent_t ef, ej;
    _SideStream() {
        cudaFree(0);
        int lo, hi;
        cudaDeviceGetStreamPriorityRange(&lo, &hi);
        cudaStreamCreateWithPriority(&s2, cudaStreamNonBlocking, lo);
        cudaEventCreateWithFlags(&ef, cudaEventDisableTiming);
        cudaEventCreateWithFlags(&ej, cudaEventDisableTiming);
    }
};
static _SideStream g_ss;

// ---------------------------------------------------------------------------
extern "C" void kernel_launch(void* const* d_in, const int* in_sizes, int n_in,
                              void* d_out, int out_size) {
    const int*   traj     = (const int*)  d_in[0];
    const float* mat1     = (const float*)d_in[1];
    const float* mat2s    = (const float*)d_in[2];
    const float* vec      = (const float*)d_in[3];
    const int*   traj_len = (const int*)  d_in[4];
    const float* emb_t    = (const float*)d_in[5];
    const float* emb_l    = (const float*)d_in[6];
    const float* emb_u    = (const float*)d_in[7];
    const float* emb_su   = (const float*)d_in[8];
    const float* emb_sl   = (const float*)d_in[9];
    const float* emb_tu   = (const float*)d_in[10];
    const float* emb_tl   = (const float*)d_in[11];
    const float* Wq       = (const float*)d_in[12];
    const float* Wk       = (const float*)d_in[13];
    const float* Wv       = (const float*)d_in[14];
    const float* W_out    = (const float*)d_in[15];
    const float* b_out    = (const float*)d_in[16];
    float* out = (float*)d_out;

    const int QKV_SMEM = (32 * LJ + 3 * 64 * LJ) * (int)sizeof(float);
    const int SC_SMEM  = (MT * LJ + 128 * LJ + MT * LSC + 8) * (int)sizeof(float);
    const int GEMM_SMEM = (2 * TILE_HB) * 2 + 128 * (int)sizeof(float);
    cudaFuncSetAttribute(qkv_kernel,    cudaFuncAttributeMaxDynamicSharedMemorySize, QKV_SMEM);
    cudaFuncSetAttribute(scores_kernel, cudaFuncAttributeMaxDynamicSharedMemorySize, SC_SMEM);
    cudaFuncSetAttribute(out_gemm_mma,  cudaFuncAttributeMaxDynamicSharedMemorySize, GEMM_SMEM);

    // main: mark; fork rowsum onto LOW-priority stream (overlaps qkv)
    mark_need_kernel<<<NB * MB / 256, 256>>>(traj);
    cudaEventRecord(g_ss.ef, 0);
    cudaStreamWaitEvent(g_ss.s2, g_ss.ef, 0);
    rowsum_kernel<<<LB, 256, 0, g_ss.s2>>>(mat2s);
    cudaEventRecord(g_ss.ej, g_ss.s2);

    // main stream: qkv (no rowsum dependency)
    qkv_kernel<<<(NB * MB) / 32, 256, QKV_SMEM>>>(traj, emb_t, emb_l, emb_u,
                                                  Wq, Wk, Wv, W_out);

    // join BEFORE scores (scores consumes g_rowsum via fused delta2)
    cudaStreamWaitEvent(0, g_ss.ej, 0);
    dim3 sg(MB / MT, NB);
    scores_kernel<<<sg, 256, SC_SMEM>>>(traj, mat1, vec, traj_len,
                                        emb_su, emb_sl, emb_tu, emb_tl);

    dim3 grid(LB / 256, (NB * MB) / 128);
    out_gemm_mma<<<grid, 256, GEMM_SMEM>>>(b_out, out);
}